// round 1
// baseline (speedup 1.0000x reference)
#include <cuda_runtime.h>
#include <cstdint>
#include <cstddef>

#define NN 50000
#define NE 800000

// ---------------- static device scratch (no allocation allowed) ----------------
__device__ int   g_cnt[NN];
__device__ int   g_rowptr[NN + 1];
__device__ int   g_srcs[NE];
__device__ float g_ps[NE];
__device__ float g_invdeg[NN];

__device__ float g_uv1[(size_t)NN * 128];   // conv1: u|v tables (post-GEMM gather)
__device__ float g_r1 [(size_t)NN * 64];    // x @ R1
__device__ float g_h  [(size_t)NN * 64];    // h after conv1 (RK state)
__device__ float g_a  [(size_t)NN * 64];    // intermediate conv_a output
__device__ float g_acat[(size_t)NN * 128];  // pre-agg A0|A1 (scaled by invdeg)
__device__ float g_y  [(size_t)NN * 64];    // RK stage inputs y2/y3/y4
__device__ float g_acc[(size_t)NN * 64];    // RK accumulator
__device__ float g_hn [(size_t)NN * 64];    // h after RK step
__device__ float g_uv2[(size_t)NN * 32];    // conv2 u|v tables
__device__ float g_r2 [(size_t)NN * 16];    // h @ R2

__device__ float g_wc1[256 * 192];          // [W1_0 | W1_1 | R1] column-concat
__device__ float g_wcA[192 * 64];           // [Wa ; Ra] row-concat
__device__ float g_wcB[192 * 64];           // [Wb ; Rb]
__device__ float g_wc2[64 * 48];            // [W2_0 | W2_1 | R2]

// ---------------- CSR build ----------------
__global__ void k_zero_cnt() {
    int i = blockIdx.x * 256 + threadIdx.x;
    if (i < NN) g_cnt[i] = 0;
}

__global__ void k_hist(const int* __restrict__ dst) {
    int e = blockIdx.x * 256 + threadIdx.x;
    if (e < NE) atomicAdd(&g_cnt[dst[e]], 1);
}

__global__ void k_scan() {
    __shared__ int wsum[32];
    int tid = threadIdx.x, lane = tid & 31, wid = tid >> 5;
    int carry = 0;
    for (int base = 0; base < NN; base += 1024) {
        int i = base + tid;
        int v = (i < NN) ? g_cnt[i] : 0;
        int x = v;
        #pragma unroll
        for (int o = 1; o < 32; o <<= 1) {
            int t = __shfl_up_sync(0xffffffffu, x, o);
            if (lane >= o) x += t;
        }
        if (lane == 31) wsum[wid] = x;
        __syncthreads();
        if (wid == 0) {
            int t = wsum[lane];
            #pragma unroll
            for (int o = 1; o < 32; o <<= 1) {
                int u = __shfl_up_sync(0xffffffffu, t, o);
                if (lane >= o) t += u;
            }
            wsum[lane] = t;
        }
        __syncthreads();
        int incl = x + (wid > 0 ? wsum[wid - 1] : 0);
        if (i < NN) {
            g_rowptr[i] = carry + incl - v;            // exclusive prefix
            g_invdeg[i] = 1.0f / (float)max(v, 1);
            g_cnt[i] = 0;                               // reset for cursor use
        }
        carry += wsum[31];
        __syncthreads();
    }
    if (tid == 0) g_rowptr[NN] = carry;
}

__global__ void k_scatter(const int* __restrict__ src, const int* __restrict__ dst,
                          const float* __restrict__ ea) {
    int e = blockIdx.x * 256 + threadIdx.x;
    if (e < NE) {
        int d = dst[e];
        int pos = g_rowptr[d] + atomicAdd(&g_cnt[d], 1);
        g_srcs[pos] = src[e];
        g_ps[pos]   = ea[e];
    }
}

// ---------------- weight concat prep ----------------
__global__ void k_prep(const float* __restrict__ W1, const float* __restrict__ R1,
                       const float* __restrict__ Wa, const float* __restrict__ Ra,
                       const float* __restrict__ Wb, const float* __restrict__ Rb,
                       const float* __restrict__ W2, const float* __restrict__ R2) {
    int i = blockIdx.x * 256 + threadIdx.x;
    if (i < 49152) {                    // g_wc1 [256][192]
        int k = i / 192, c = i % 192;
        float v;
        if (c < 64)        v = W1[k * 64 + c];
        else if (c < 128)  v = W1[(256 + k) * 64 + (c - 64)];
        else               v = R1[k * 64 + (c - 128)];
        g_wc1[i] = v;
    } else if (i < 61440) {             // g_wcA [192][64]
        int j = i - 49152, k = j / 64, c = j % 64;
        g_wcA[j] = (k < 128) ? Wa[k * 64 + c] : Ra[(k - 128) * 64 + c];
    } else if (i < 73728) {             // g_wcB [192][64]
        int j = i - 61440, k = j / 64, c = j % 64;
        g_wcB[j] = (k < 128) ? Wb[k * 64 + c] : Rb[(k - 128) * 64 + c];
    } else if (i < 76800) {             // g_wc2 [64][48]
        int j = i - 73728, k = j / 48, c = j % 48;
        float v;
        if (c < 16)       v = W2[k * 16 + c];
        else if (c < 32)  v = W2[(64 + k) * 16 + (c - 16)];
        else              v = R2[k * 16 + (c - 32)];
        g_wc2[j] = v;
    }
}

// ---------------- tf32 GEMM with fused epilogues ----------------
__device__ __forceinline__ uint32_t f2tf(float f) {
    uint32_t r;
    asm("cvt.rna.tf32.f32 %0, %1;" : "=r"(r) : "f"(f));
    return r;
}

__device__ __forceinline__ void mma8(float* c, uint32_t a0, uint32_t a1, uint32_t a2,
                                     uint32_t a3, uint32_t b0, uint32_t b1) {
    asm volatile(
        "mma.sync.aligned.m16n8k8.row.col.f32.tf32.tf32.f32 "
        "{%0,%1,%2,%3},{%4,%5,%6,%7},{%8,%9},{%0,%1,%2,%3};"
        : "+f"(c[0]), "+f"(c[1]), "+f"(c[2]), "+f"(c[3])
        : "r"(a0), "r"(a1), "r"(a2), "r"(a3), "r"(b0), "r"(b1));
}

constexpr int M_CONV1 = 0, M_PLAIN = 1, M_K1 = 2, M_K2 = 3, M_K3 = 4, M_K4 = 5, M_CONV2 = 6;

// ASEL: 0=arg xin, 1=g_acat, 2=g_hn ; BSEL: 0=g_h, 1=g_a, 2=g_y ; WSEL: 0..3
template <int K1, int K2, int NOUT, int BN, int MODE, int ASEL, int BSEL, int WSEL>
__global__ __launch_bounds__(256, 2)
void gemm_k(const float* __restrict__ xin, const float* __restrict__ bias) {
    constexpr int K = K1 + K2;
    constexpr int NF = BN / 16;
    __shared__ uint32_t As[128][36];
    __shared__ uint32_t Bs[32][72];

    const float* baseA;
    if constexpr (ASEL == 0) baseA = xin;
    else if constexpr (ASEL == 1) baseA = g_acat;
    else baseA = g_hn;
    const float* baseB;
    if constexpr (BSEL == 0) baseB = g_h;
    else if constexpr (BSEL == 1) baseB = g_a;
    else baseB = g_y;
    const float* Wp;
    if constexpr (WSEL == 0) Wp = g_wc1;
    else if constexpr (WSEL == 1) Wp = g_wcA;
    else if constexpr (WSEL == 2) Wp = g_wcB;
    else Wp = g_wc2;

    const int tid = threadIdx.x;
    const int m0 = blockIdx.x * 128;
    const int n0 = blockIdx.y * BN;
    const int wid = tid >> 5, lane = tid & 31;
    const int wm = (wid & 3) * 32;
    const int wn = (wid >> 2) * (BN / 2);
    const int g = lane >> 2, t = lane & 3;

    float acc[2][NF][4];
    #pragma unroll
    for (int i = 0; i < 2; i++)
        #pragma unroll
        for (int j = 0; j < NF; j++)
            #pragma unroll
            for (int e = 0; e < 4; e++) acc[i][j][e] = 0.f;

    for (int kc = 0; kc < K; kc += 32) {
        __syncthreads();
        #pragma unroll
        for (int i = 0; i < 4; i++) {
            int q = tid + i * 256;
            int row = q >> 3, kq = (q & 7) * 4;
            int gm = m0 + row;
            float4 v = make_float4(0.f, 0.f, 0.f, 0.f);
            if (gm < NN) {
                const float* p = (kc < K1)
                    ? (baseA + (size_t)gm * K1 + kc + kq)
                    : (baseB + (size_t)gm * K2 + (kc - K1) + kq);
                v = *reinterpret_cast<const float4*>(p);
            }
            As[row][kq + 0] = f2tf(v.x);
            As[row][kq + 1] = f2tf(v.y);
            As[row][kq + 2] = f2tf(v.z);
            As[row][kq + 3] = f2tf(v.w);
        }
        #pragma unroll
        for (int i = 0; i < (32 * BN) / 256; i++) {
            int q = tid + i * 256;
            int kk = q / BN, n = q % BN;
            Bs[kk][n] = f2tf(Wp[(size_t)(kc + kk) * NOUT + n0 + n]);
        }
        __syncthreads();
        #pragma unroll
        for (int ks = 0; ks < 4; ks++) {
            const int kb = ks * 8;
            uint32_t a[2][4];
            #pragma unroll
            for (int mf = 0; mf < 2; mf++) {
                a[mf][0] = As[wm + mf * 16 + g    ][kb + t];
                a[mf][1] = As[wm + mf * 16 + g + 8][kb + t];
                a[mf][2] = As[wm + mf * 16 + g    ][kb + t + 4];
                a[mf][3] = As[wm + mf * 16 + g + 8][kb + t + 4];
            }
            uint32_t b[NF][2];
            #pragma unroll
            for (int nf = 0; nf < NF; nf++) {
                b[nf][0] = Bs[kb + t    ][wn + nf * 8 + g];
                b[nf][1] = Bs[kb + t + 4][wn + nf * 8 + g];
            }
            #pragma unroll
            for (int mf = 0; mf < 2; mf++)
                #pragma unroll
                for (int nf = 0; nf < NF; nf++)
                    mma8(acc[mf][nf], a[mf][0], a[mf][1], a[mf][2], a[mf][3],
                         b[nf][0], b[nf][1]);
        }
    }

    // epilogue
    #pragma unroll
    for (int mf = 0; mf < 2; mf++) {
        #pragma unroll
        for (int nf = 0; nf < NF; nf++) {
            #pragma unroll
            for (int e = 0; e < 4; e++) {
                int gm = m0 + wm + mf * 16 + g + ((e >= 2) ? 8 : 0);
                int gc = n0 + wn + nf * 8 + t * 2 + (e & 1);
                if (gm >= NN) continue;
                float v = acc[mf][nf][e];
                if constexpr (MODE == M_CONV1) {
                    if (gc < 128) g_uv1[(size_t)gm * 128 + gc] = v;
                    else          g_r1[(size_t)gm * 64 + gc - 128] = v;
                } else if constexpr (MODE == M_PLAIN) {
                    g_a[(size_t)gm * 64 + gc] = v + bias[gc];
                } else if constexpr (MODE == M_K1) {
                    float k = v + bias[gc];
                    size_t ix = (size_t)gm * 64 + gc;
                    float hh = g_h[ix];
                    g_y[ix]   = hh + 1.5f * k;
                    g_acc[ix] = hh + 0.5f * k;
                } else if constexpr (MODE == M_K2) {
                    float k = v + bias[gc];
                    size_t ix = (size_t)gm * 64 + gc;
                    float hh = g_h[ix];
                    g_y[ix]   = hh + 1.5f * k;
                    g_acc[ix] = g_acc[ix] + k;
                } else if constexpr (MODE == M_K3) {
                    float k = v + bias[gc];
                    size_t ix = (size_t)gm * 64 + gc;
                    float hh = g_h[ix];
                    g_y[ix]   = hh + 3.0f * k;
                    g_acc[ix] = g_acc[ix] + k;
                } else if constexpr (MODE == M_K4) {
                    float k = v + bias[gc];
                    size_t ix = (size_t)gm * 64 + gc;
                    g_hn[ix] = g_acc[ix] + 0.5f * k;
                } else {  // M_CONV2
                    if (gc < 32) g_uv2[(size_t)gm * 32 + gc] = v;
                    else         g_r2[(size_t)gm * 16 + gc - 32] = v;
                }
            }
        }
    }
}

// ---------------- aggregation kernels (warp per node, gather via CSR) ----------------
// conv1 post-GEMM gather: h = tanh( mean_e[(1-p)u[s] + p v[s]] + r1 + b1 )
__global__ __launch_bounds__(256)
void agg_post1(const float* __restrict__ b1) {
    int node = (blockIdx.x << 3) + (threadIdx.x >> 5);
    int lane = threadIdx.x & 31;
    int beg = g_rowptr[node], end = g_rowptr[node + 1];
    float mx = 0.f, my = 0.f;
    int e = beg;
    for (; e + 2 <= end; e += 2) {
        int s0 = g_srcs[e], s1 = g_srcs[e + 1];
        float p0 = g_ps[e], p1 = g_ps[e + 1];
        float2 u0 = *(const float2*)(g_uv1 + (size_t)s0 * 128 + lane * 2);
        float2 v0 = *(const float2*)(g_uv1 + (size_t)s0 * 128 + 64 + lane * 2);
        float2 u1 = *(const float2*)(g_uv1 + (size_t)s1 * 128 + lane * 2);
        float2 v1 = *(const float2*)(g_uv1 + (size_t)s1 * 128 + 64 + lane * 2);
        mx += (1.f - p0) * u0.x + p0 * v0.x + (1.f - p1) * u1.x + p1 * v1.x;
        my += (1.f - p0) * u0.y + p0 * v0.y + (1.f - p1) * u1.y + p1 * v1.y;
    }
    if (e < end) {
        int s0 = g_srcs[e];
        float p0 = g_ps[e];
        float2 u0 = *(const float2*)(g_uv1 + (size_t)s0 * 128 + lane * 2);
        float2 v0 = *(const float2*)(g_uv1 + (size_t)s0 * 128 + 64 + lane * 2);
        mx += (1.f - p0) * u0.x + p0 * v0.x;
        my += (1.f - p0) * u0.y + p0 * v0.y;
    }
    float id = g_invdeg[node];
    size_t ix = (size_t)node * 64 + lane * 2;
    g_h[ix]     = tanhf(mx * id + g_r1[ix]     + b1[lane * 2]);
    g_h[ix + 1] = tanhf(my * id + g_r1[ix + 1] + b1[lane * 2 + 1]);
}

// hidden pre-agg: A0 = invdeg * sum (1-p) y[s], A1 = invdeg * sum p y[s] -> g_acat
template <int YSEL>  // 0=g_h, 1=g_a, 2=g_y
__global__ __launch_bounds__(256)
void agg_pre() {
    const float* __restrict__ y = (YSEL == 0) ? g_h : ((YSEL == 1) ? g_a : g_y);
    int node = (blockIdx.x << 3) + (threadIdx.x >> 5);
    int lane = threadIdx.x & 31;
    int beg = g_rowptr[node], end = g_rowptr[node + 1];
    float a0x = 0.f, a0y = 0.f, a1x = 0.f, a1y = 0.f;
    int e = beg;
    for (; e + 2 <= end; e += 2) {
        int s0 = g_srcs[e], s1 = g_srcs[e + 1];
        float p0 = g_ps[e], p1 = g_ps[e + 1];
        float2 x0 = *(const float2*)(y + (size_t)s0 * 64 + lane * 2);
        float2 x1 = *(const float2*)(y + (size_t)s1 * 64 + lane * 2);
        a0x += (1.f - p0) * x0.x + (1.f - p1) * x1.x;
        a0y += (1.f - p0) * x0.y + (1.f - p1) * x1.y;
        a1x += p0 * x0.x + p1 * x1.x;
        a1y += p0 * x0.y + p1 * x1.y;
    }
    if (e < end) {
        int s0 = g_srcs[e];
        float p0 = g_ps[e];
        float2 x0 = *(const float2*)(y + (size_t)s0 * 64 + lane * 2);
        a0x += (1.f - p0) * x0.x;
        a0y += (1.f - p0) * x0.y;
        a1x += p0 * x0.x;
        a1y += p0 * x0.y;
    }
    float id = g_invdeg[node];
    float2* o0 = (float2*)(g_acat + (size_t)node * 128 + lane * 2);
    float2* o1 = (float2*)(g_acat + (size_t)node * 128 + 64 + lane * 2);
    *o0 = make_float2(a0x * id, a0y * id);
    *o1 = make_float2(a1x * id, a1y * id);
}

// conv2: gather + tanh + log_softmax(16). 16 threads per node.
__global__ __launch_bounds__(256)
void conv2_fin(const float* __restrict__ b2, float* __restrict__ out) {
    int node = blockIdx.x * 16 + (threadIdx.x >> 4);
    int c = threadIdx.x & 15;
    int beg = g_rowptr[node], end = g_rowptr[node + 1];
    float m = 0.f;
    for (int e = beg; e < end; e++) {
        int s = g_srcs[e];
        float p = g_ps[e];
        m += (1.f - p) * g_uv2[(size_t)s * 32 + c] + p * g_uv2[(size_t)s * 32 + 16 + c];
    }
    float o = tanhf(m * g_invdeg[node] + g_r2[(size_t)node * 16 + c] + b2[c]);
    float mx = o;
    #pragma unroll
    for (int k = 8; k; k >>= 1) mx = fmaxf(mx, __shfl_xor_sync(0xffffffffu, mx, k));
    float s = expf(o - mx);
    float tot = s;
    #pragma unroll
    for (int k = 8; k; k >>= 1) tot += __shfl_xor_sync(0xffffffffu, tot, k);
    out[(size_t)node * 16 + c] = o - mx - logf(tot);
}

// ---------------- launch ----------------
extern "C" void kernel_launch(void* const* d_in, const int* in_sizes, int n_in,
                              void* d_out, int out_size) {
    const float* x   = (const float*)d_in[0];
    const float* ea  = (const float*)d_in[1];
    const int*   src = (const int*)  d_in[2];
    const int*   dst = (const int*)  d_in[3];
    const float* W1  = (const float*)d_in[4];
    const float* R1  = (const float*)d_in[5];
    const float* b1  = (const float*)d_in[6];
    const float* Wa  = (const float*)d_in[7];
    const float* Ra  = (const float*)d_in[8];
    const float* ba  = (const float*)d_in[9];
    const float* Wb  = (const float*)d_in[10];
    const float* Rb  = (const float*)d_in[11];
    const float* bb  = (const float*)d_in[12];
    const float* W2  = (const float*)d_in[13];
    const float* R2  = (const float*)d_in[14];
    const float* b2  = (const float*)d_in[15];
    float* out = (float*)d_out;

    // CSR build (per launch — graph is an input)
    k_zero_cnt<<<196, 256>>>();
    k_hist<<<3125, 256>>>(dst);
    k_scan<<<1, 1024>>>();
    k_scatter<<<3125, 256>>>(src, dst, ea);
    k_prep<<<300, 256>>>(W1, R1, Wa, Ra, Wb, Rb, W2, R2);

    dim3 g1(391, 3), gh(391, 1);

    // conv1: u|v|r GEMM then post-gather + tanh
    gemm_k<256, 0, 192, 64, M_CONV1, 0, 0, 0><<<g1, 256>>>(x, nullptr);
    agg_post1<<<6250, 256>>>(b1);

    // RK4 stage 1: k1 = f(h)
    agg_pre<0><<<6250, 256>>>();
    gemm_k<128, 64, 64, 64, M_PLAIN, 1, 0, 1><<<gh, 256>>>(nullptr, ba);
    agg_pre<1><<<6250, 256>>>();
    gemm_k<128, 64, 64, 64, M_K1, 1, 1, 2><<<gh, 256>>>(nullptr, bb);

    // stage 2: k2 = f(y2)
    agg_pre<2><<<6250, 256>>>();
    gemm_k<128, 64, 64, 64, M_PLAIN, 1, 2, 1><<<gh, 256>>>(nullptr, ba);
    agg_pre<1><<<6250, 256>>>();
    gemm_k<128, 64, 64, 64, M_K2, 1, 1, 2><<<gh, 256>>>(nullptr, bb);

    // stage 3: k3 = f(y3)
    agg_pre<2><<<6250, 256>>>();
    gemm_k<128, 64, 64, 64, M_PLAIN, 1, 2, 1><<<gh, 256>>>(nullptr, ba);
    agg_pre<1><<<6250, 256>>>();
    gemm_k<128, 64, 64, 64, M_K3, 1, 1, 2><<<gh, 256>>>(nullptr, bb);

    // stage 4: k4 = f(y4); h_new = acc + 0.5 k4
    agg_pre<2><<<6250, 256>>>();
    gemm_k<128, 64, 64, 64, M_PLAIN, 1, 2, 1><<<gh, 256>>>(nullptr, ba);
    agg_pre<1><<<6250, 256>>>();
    gemm_k<128, 64, 64, 64, M_K4, 1, 1, 2><<<gh, 256>>>(nullptr, bb);

    // conv2 + tanh + log_softmax
    gemm_k<64, 0, 48, 48, M_CONV2, 2, 0, 3><<<gh, 256>>>(nullptr, nullptr);
    conv2_fin<<<3125, 256>>>(b2, out);
}

// round 2
// speedup vs baseline: 1.2941x; 1.2941x over previous
#include <cuda_runtime.h>
#include <cuda_bf16.h>
#include <cstdint>
#include <cstddef>

#define NN 50000
#define NE 800000

// ---------------- static device scratch ----------------
__device__ int   g_cnt[NN];
__device__ int   g_rowptr[NN + 1];
__device__ int   g_bsum[64];
__device__ int   g_srcs[NE];
__device__ float g_ps[NE];
__device__ float g_invdeg[NN];

// bf16x2-packed tables (u32 each = 2 features)
__device__ __align__(16) unsigned g_uv1 [(size_t)NN * 64];  // conv1 u|v (128 feats)
__device__ __align__(16) unsigned g_h16 [(size_t)NN * 32];
__device__ __align__(16) unsigned g_a16 [(size_t)NN * 32];
__device__ __align__(16) unsigned g_y16 [(size_t)NN * 32];
__device__ __align__(16) unsigned g_hn16[(size_t)NN * 32];
__device__ __align__(16) unsigned g_acat[(size_t)NN * 64];  // A0|A1 (128 feats)
__device__ __align__(16) unsigned g_uv2 [(size_t)NN * 16];  // conv2 u|v (32 feats)

// fp32 state
__device__ float g_r1  [(size_t)NN * 64];
__device__ float g_hf  [(size_t)NN * 64];
__device__ float g_accf[(size_t)NN * 64];
__device__ float g_r2  [(size_t)NN * 16];

// packed weights: [k/2][n] u32 = bf16(k even)|bf16(k odd)
__device__ unsigned g_wc1[128 * 192];  // conv1 [W1_0|W1_1|R1], K=256
__device__ unsigned g_wcA[96 * 64];    // [Wa;Ra], K=192
__device__ unsigned g_wcB[96 * 64];    // [Wb;Rb]
__device__ unsigned g_wc2[32 * 48];    // conv2 [W2_0|W2_1|R2], K=64

// ---------------- helpers ----------------
__device__ __forceinline__ unsigned pk(float a, float b) {
    __nv_bfloat162 h = __floats2bfloat162_rn(a, b);
    return *reinterpret_cast<unsigned*>(&h);
}
__device__ __forceinline__ float2 up(unsigned u) {
    __nv_bfloat162 h = *reinterpret_cast<__nv_bfloat162*>(&u);
    return make_float2(__bfloat162float(h.x), __bfloat162float(h.y));
}
__device__ __forceinline__ float bfh(unsigned u, int hi) {
    unsigned short s = hi ? (unsigned short)(u >> 16) : (unsigned short)(u & 0xffff);
    __nv_bfloat16 b = *reinterpret_cast<__nv_bfloat16*>(&s);
    return __bfloat162float(b);
}

// ---------------- CSR build ----------------
__global__ void k_zero_cnt() {
    int i = blockIdx.x * 256 + threadIdx.x;
    if (i < NN) g_cnt[i] = 0;
}

__global__ void k_hist(const int* __restrict__ dst) {
    int e = blockIdx.x * 256 + threadIdx.x;
    if (e < NE) atomicAdd(&g_cnt[dst[e]], 1);
}

// block-local exclusive scan; zero cnt for cursor use; write block total
__global__ void k_scan1() {
    __shared__ int ws[32];
    int tid = threadIdx.x, lane = tid & 31, wid = tid >> 5;
    int i = blockIdx.x * 1024 + tid;
    int v = (i < NN) ? g_cnt[i] : 0;
    int x = v;
    #pragma unroll
    for (int o = 1; o < 32; o <<= 1) {
        int t = __shfl_up_sync(0xffffffffu, x, o);
        if (lane >= o) x += t;
    }
    if (lane == 31) ws[wid] = x;
    __syncthreads();
    if (wid == 0) {
        int t = ws[lane];
        #pragma unroll
        for (int o = 1; o < 32; o <<= 1) {
            int u = __shfl_up_sync(0xffffffffu, t, o);
            if (lane >= o) t += u;
        }
        ws[lane] = t;
    }
    __syncthreads();
    int excl = x - v + (wid ? ws[wid - 1] : 0);
    if (i < NN) {
        g_rowptr[i] = excl;
        g_invdeg[i] = 1.0f / (float)max(v, 1);
        g_cnt[i] = 0;
    }
    if (tid == 1023) g_bsum[blockIdx.x] = excl + v;
}

__global__ void k_scan2() {
    __shared__ int w2[2];
    int tid = threadIdx.x, lane = tid & 31, wid = tid >> 5;
    int v = (tid < 49) ? g_bsum[tid] : 0;
    int x = v;
    #pragma unroll
    for (int o = 1; o < 32; o <<= 1) {
        int t = __shfl_up_sync(0xffffffffu, x, o);
        if (lane >= o) x += t;
    }
    if (lane == 31) w2[wid] = x;
    __syncthreads();
    int incl = x + (wid == 1 ? w2[0] : 0);
    if (tid < 49) g_bsum[tid] = incl - v;
}

__global__ void k_scan3() {
    int i = blockIdx.x * 1024 + threadIdx.x;
    if (i < NN) g_rowptr[i] += g_bsum[blockIdx.x];
    if (i == 0) g_rowptr[NN] = NE;
}

__global__ void k_scatter(const int* __restrict__ src, const int* __restrict__ dst,
                          const float* __restrict__ ea) {
    int e = blockIdx.x * 256 + threadIdx.x;
    if (e < NE) {
        int d = dst[e];
        int pos = g_rowptr[d] + atomicAdd(&g_cnt[d], 1);
        g_srcs[pos] = src[e];
        g_ps[pos]   = ea[e];
    }
}

// ---------------- weight prep (pack bf16 pairs) ----------------
__global__ void k_prep(const float* __restrict__ W1, const float* __restrict__ R1,
                       const float* __restrict__ Wa, const float* __restrict__ Ra,
                       const float* __restrict__ Wb, const float* __restrict__ Rb,
                       const float* __restrict__ W2, const float* __restrict__ R2) {
    int i = blockIdx.x * 256 + threadIdx.x;
    if (i < 24576) {                        // g_wc1 [128][192], K=256
        int k2 = i / 192, c = i % 192;
        int ke = 2 * k2, ko = ke + 1;
        float e, o;
        if (c < 64)       { e = W1[ke * 64 + c];            o = W1[ko * 64 + c]; }
        else if (c < 128) { e = W1[(256 + ke) * 64 + c - 64]; o = W1[(256 + ko) * 64 + c - 64]; }
        else              { e = R1[ke * 64 + c - 128];      o = R1[ko * 64 + c - 128]; }
        g_wc1[i] = pk(e, o);
    } else if (i < 30720) {                 // g_wcA [96][64], K=192
        int j = i - 24576, k2 = j / 64, c = j % 64;
        int ke = 2 * k2, ko = ke + 1;
        float e = (ke < 128) ? Wa[ke * 64 + c] : Ra[(ke - 128) * 64 + c];
        float o = (ko < 128) ? Wa[ko * 64 + c] : Ra[(ko - 128) * 64 + c];
        g_wcA[j] = pk(e, o);
    } else if (i < 36864) {                 // g_wcB
        int j = i - 30720, k2 = j / 64, c = j % 64;
        int ke = 2 * k2, ko = ke + 1;
        float e = (ke < 128) ? Wb[ke * 64 + c] : Rb[(ke - 128) * 64 + c];
        float o = (ko < 128) ? Wb[ko * 64 + c] : Rb[(ko - 128) * 64 + c];
        g_wcB[j] = pk(e, o);
    } else if (i < 38400) {                 // g_wc2 [32][48], K=64
        int j = i - 36864, k2 = j / 48, c = j % 48;
        int ke = 2 * k2, ko = ke + 1;
        float e, o;
        if (c < 16)      { e = W2[ke * 16 + c];            o = W2[ko * 16 + c]; }
        else if (c < 32) { e = W2[(64 + ke) * 16 + c - 16]; o = W2[(64 + ko) * 16 + c - 16]; }
        else             { e = R2[ke * 16 + c - 32];       o = R2[ko * 16 + c - 32]; }
        g_wc2[j] = pk(e, o);
    }
}

// ---------------- bf16 GEMM (m16n8k16) with fused epilogues ----------------
__device__ __forceinline__ void mma16(float* c, unsigned a0, unsigned a1, unsigned a2,
                                      unsigned a3, unsigned b0, unsigned b1) {
    asm volatile(
        "mma.sync.aligned.m16n8k16.row.col.f32.bf16.bf16.f32 "
        "{%0,%1,%2,%3},{%4,%5,%6,%7},{%8,%9},{%0,%1,%2,%3};"
        : "+f"(c[0]), "+f"(c[1]), "+f"(c[2]), "+f"(c[3])
        : "r"(a0), "r"(a1), "r"(a2), "r"(a3), "r"(b0), "r"(b1));
}

constexpr int M_CONV1 = 0, M_PLAIN = 1, M_K1 = 2, M_K2 = 3, M_K3 = 4, M_K4 = 5, M_CONV2 = 6;

template <int MODE>
__device__ __forceinline__ void epi_row(int gm, int gc, float v0, float v1,
                                        const float* __restrict__ bias) {
    if (gm >= NN) return;
    if constexpr (MODE == M_CONV1) {
        if (gc < 128) g_uv1[(size_t)gm * 64 + (gc >> 1)] = pk(v0, v1);
        else { g_r1[(size_t)gm * 64 + gc - 128] = v0; g_r1[(size_t)gm * 64 + gc - 127] = v1; }
    } else if constexpr (MODE == M_PLAIN) {
        g_a16[(size_t)gm * 32 + (gc >> 1)] = pk(v0 + bias[gc], v1 + bias[gc + 1]);
    } else if constexpr (MODE == M_K1) {
        size_t ix = (size_t)gm * 64 + gc;
        float k0 = v0 + bias[gc], k1 = v1 + bias[gc + 1];
        float h0 = g_hf[ix], h1 = g_hf[ix + 1];
        g_y16[(size_t)gm * 32 + (gc >> 1)] = pk(h0 + 1.5f * k0, h1 + 1.5f * k1);
        g_accf[ix] = h0 + 0.5f * k0; g_accf[ix + 1] = h1 + 0.5f * k1;
    } else if constexpr (MODE == M_K2) {
        size_t ix = (size_t)gm * 64 + gc;
        float k0 = v0 + bias[gc], k1 = v1 + bias[gc + 1];
        float h0 = g_hf[ix], h1 = g_hf[ix + 1];
        g_y16[(size_t)gm * 32 + (gc >> 1)] = pk(h0 + 1.5f * k0, h1 + 1.5f * k1);
        g_accf[ix] += k0; g_accf[ix + 1] += k1;
    } else if constexpr (MODE == M_K3) {
        size_t ix = (size_t)gm * 64 + gc;
        float k0 = v0 + bias[gc], k1 = v1 + bias[gc + 1];
        float h0 = g_hf[ix], h1 = g_hf[ix + 1];
        g_y16[(size_t)gm * 32 + (gc >> 1)] = pk(h0 + 3.0f * k0, h1 + 3.0f * k1);
        g_accf[ix] += k0; g_accf[ix + 1] += k1;
    } else if constexpr (MODE == M_K4) {
        size_t ix = (size_t)gm * 64 + gc;
        float k0 = v0 + bias[gc], k1 = v1 + bias[gc + 1];
        g_hn16[(size_t)gm * 32 + (gc >> 1)] = pk(g_accf[ix] + 0.5f * k0,
                                                 g_accf[ix + 1] + 0.5f * k1);
    } else {  // M_CONV2
        if (gc < 32) g_uv2[(size_t)gm * 16 + (gc >> 1)] = pk(v0, v1);
        else { g_r2[(size_t)gm * 16 + gc - 32] = v0; g_r2[(size_t)gm * 16 + gc - 31] = v1; }
    }
}

// ASEL: 0=conv1 (fp32 xin, K=256), 1=hidden (acat128 | ytab64), 2=conv2 (g_hn16)
// WSEL: 0=wc1 1=wcA 2=wcB 3=wc2 ; TSEL: 0=h16 1=a16 2=y16
template <int K, int NOUT, int BN, int MODE, int ASEL, int WSEL, int TSEL>
__global__ __launch_bounds__(256)
void gemm16(const float* __restrict__ xin, const float* __restrict__ bias) {
    constexpr int NF = BN / 16;
    __shared__ __align__(16) unsigned As[128][36];   // stride 36 u32: bank-disjoint
    __shared__ unsigned Bs[32][72];                  // stride 72 u32: bank-disjoint

    const unsigned* Wp = (WSEL == 0) ? g_wc1 : (WSEL == 1) ? g_wcA
                       : (WSEL == 2) ? g_wcB : g_wc2;
    const unsigned* ytab = (TSEL == 0) ? g_h16 : (TSEL == 1) ? g_a16 : g_y16;

    const int tid = threadIdx.x;
    const int m0 = blockIdx.x * 128;
    const int n0 = blockIdx.y * BN;
    const int wid = tid >> 5, lane = tid & 31;
    const int wm = (wid & 3) * 32;
    const int wn = (wid >> 2) * (BN / 2);
    const int g = lane >> 2, t = lane & 3;

    float acc[2][NF][4];
    #pragma unroll
    for (int i = 0; i < 2; i++)
        #pragma unroll
        for (int j = 0; j < NF; j++)
            #pragma unroll
            for (int e = 0; e < 4; e++) acc[i][j][e] = 0.f;

    for (int kc = 0; kc < K; kc += 64) {
        __syncthreads();
        if constexpr (ASEL == 0) {
            #pragma unroll
            for (int i = 0; i < 8; i++) {
                int q = tid + i * 256;
                int row = q >> 4, f4 = q & 15;
                int gm = m0 + row;
                float4 v = make_float4(0.f, 0.f, 0.f, 0.f);
                if (gm < NN)
                    v = *reinterpret_cast<const float4*>(xin + (size_t)gm * 256 + kc + f4 * 4);
                As[row][f4 * 2]     = pk(v.x, v.y);
                As[row][f4 * 2 + 1] = pk(v.z, v.w);
            }
        } else {
            #pragma unroll
            for (int i = 0; i < 4; i++) {
                int q = tid + i * 256;
                int row = q >> 3, q4 = q & 7;
                int gm = m0 + row;
                uint4 v = make_uint4(0, 0, 0, 0);
                if (gm < NN) {
                    const unsigned* p;
                    if constexpr (ASEL == 1)
                        p = (kc < 128) ? (g_acat + (size_t)gm * 64 + kc / 2 + q4 * 4)
                                       : (ytab + (size_t)gm * 32 + q4 * 4);
                    else
                        p = g_hn16 + (size_t)gm * 32 + q4 * 4;
                    v = *reinterpret_cast<const uint4*>(p);
                }
                *reinterpret_cast<uint4*>(&As[row][q4 * 4]) = v;
            }
        }
        constexpr int BITER = (32 * BN) / 256;
        #pragma unroll
        for (int i = 0; i < BITER; i++) {
            int q = tid + i * 256;
            int r = q / BN, n = q % BN;
            Bs[r][n] = Wp[(size_t)(kc / 2 + r) * NOUT + n0 + n];
        }
        __syncthreads();
        #pragma unroll
        for (int ks = 0; ks < 4; ks++) {
            const int kb = ks * 8;
            unsigned a[2][4];
            #pragma unroll
            for (int mf = 0; mf < 2; mf++) {
                a[mf][0] = As[wm + mf * 16 + g    ][kb + t];
                a[mf][1] = As[wm + mf * 16 + g + 8][kb + t];
                a[mf][2] = As[wm + mf * 16 + g    ][kb + 4 + t];
                a[mf][3] = As[wm + mf * 16 + g + 8][kb + 4 + t];
            }
            unsigned b[NF][2];
            #pragma unroll
            for (int nf = 0; nf < NF; nf++) {
                b[nf][0] = Bs[kb + t    ][wn + nf * 8 + g];
                b[nf][1] = Bs[kb + 4 + t][wn + nf * 8 + g];
            }
            #pragma unroll
            for (int mf = 0; mf < 2; mf++)
                #pragma unroll
                for (int nf = 0; nf < NF; nf++)
                    mma16(acc[mf][nf], a[mf][0], a[mf][1], a[mf][2], a[mf][3],
                          b[nf][0], b[nf][1]);
        }
    }

    #pragma unroll
    for (int mf = 0; mf < 2; mf++)
        #pragma unroll
        for (int nf = 0; nf < NF; nf++) {
            int gm0 = m0 + wm + mf * 16 + g;
            int gc  = n0 + wn + nf * 8 + t * 2;
            epi_row<MODE>(gm0,     gc, acc[mf][nf][0], acc[mf][nf][1], bias);
            epi_row<MODE>(gm0 + 8, gc, acc[mf][nf][2], acc[mf][nf][3], bias);
        }
}

// ---------------- aggregation (warp per node, bf16 gather) ----------------
__global__ __launch_bounds__(256)
void agg_post1(const float* __restrict__ b1) {
    int node = (blockIdx.x << 3) + (threadIdx.x >> 5);
    int lane = threadIdx.x & 31;
    int beg = g_rowptr[node], end = g_rowptr[node + 1];
    float mx = 0.f, my = 0.f;
    int e = beg;
    for (; e + 2 <= end; e += 2) {
        int s0 = g_srcs[e], s1 = g_srcs[e + 1];
        float p0 = g_ps[e], p1 = g_ps[e + 1];
        float2 u0 = up(g_uv1[(size_t)s0 * 64 + lane]);
        float2 v0 = up(g_uv1[(size_t)s0 * 64 + 32 + lane]);
        float2 u1 = up(g_uv1[(size_t)s1 * 64 + lane]);
        float2 v1 = up(g_uv1[(size_t)s1 * 64 + 32 + lane]);
        mx += (1.f - p0) * u0.x + p0 * v0.x + (1.f - p1) * u1.x + p1 * v1.x;
        my += (1.f - p0) * u0.y + p0 * v0.y + (1.f - p1) * u1.y + p1 * v1.y;
    }
    if (e < end) {
        int s0 = g_srcs[e];
        float p0 = g_ps[e];
        float2 u0 = up(g_uv1[(size_t)s0 * 64 + lane]);
        float2 v0 = up(g_uv1[(size_t)s0 * 64 + 32 + lane]);
        mx += (1.f - p0) * u0.x + p0 * v0.x;
        my += (1.f - p0) * u0.y + p0 * v0.y;
    }
    float id = g_invdeg[node];
    size_t ix = (size_t)node * 64 + lane * 2;
    float h0 = tanhf(mx * id + g_r1[ix]     + b1[lane * 2]);
    float h1 = tanhf(my * id + g_r1[ix + 1] + b1[lane * 2 + 1]);
    g_hf[ix] = h0; g_hf[ix + 1] = h1;
    g_h16[(size_t)node * 32 + lane] = pk(h0, h1);
}

template <int YSEL>  // 0=g_h16, 1=g_a16, 2=g_y16
__global__ __launch_bounds__(256)
void agg_pre() {
    const unsigned* __restrict__ y = (YSEL == 0) ? g_h16 : (YSEL == 1) ? g_a16 : g_y16;
    int node = (blockIdx.x << 3) + (threadIdx.x >> 5);
    int lane = threadIdx.x & 31;
    int beg = g_rowptr[node], end = g_rowptr[node + 1];
    float a0x = 0.f, a0y = 0.f, a1x = 0.f, a1y = 0.f;
    int e = beg;
    for (; e + 2 <= end; e += 2) {
        int s0 = g_srcs[e], s1 = g_srcs[e + 1];
        float p0 = g_ps[e], p1 = g_ps[e + 1];
        float2 x0 = up(y[(size_t)s0 * 32 + lane]);
        float2 x1 = up(y[(size_t)s1 * 32 + lane]);
        a0x += (1.f - p0) * x0.x + (1.f - p1) * x1.x;
        a0y += (1.f - p0) * x0.y + (1.f - p1) * x1.y;
        a1x += p0 * x0.x + p1 * x1.x;
        a1y += p0 * x0.y + p1 * x1.y;
    }
    if (e < end) {
        int s0 = g_srcs[e];
        float p0 = g_ps[e];
        float2 x0 = up(y[(size_t)s0 * 32 + lane]);
        a0x += (1.f - p0) * x0.x;
        a0y += (1.f - p0) * x0.y;
        a1x += p0 * x0.x;
        a1y += p0 * x0.y;
    }
    float id = g_invdeg[node];
    g_acat[(size_t)node * 64 + lane]      = pk(a0x * id, a0y * id);
    g_acat[(size_t)node * 64 + 32 + lane] = pk(a1x * id, a1y * id);
}

// conv2: gather + tanh + log_softmax(16); 16 threads per node
__global__ __launch_bounds__(256)
void conv2_fin(const float* __restrict__ b2, float* __restrict__ out) {
    int node = blockIdx.x * 16 + (threadIdx.x >> 4);
    int c = threadIdx.x & 15;
    int beg = g_rowptr[node], end = g_rowptr[node + 1];
    float m = 0.f;
    for (int e = beg; e < end; e++) {
        int s = g_srcs[e];
        float p = g_ps[e];
        float u = bfh(g_uv2[(size_t)s * 16 + (c >> 1)], c & 1);
        float v = bfh(g_uv2[(size_t)s * 16 + 8 + (c >> 1)], c & 1);
        m += (1.f - p) * u + p * v;
    }
    float o = tanhf(m * g_invdeg[node] + g_r2[(size_t)node * 16 + c] + b2[c]);
    float mx = o;
    #pragma unroll
    for (int k = 8; k; k >>= 1) mx = fmaxf(mx, __shfl_xor_sync(0xffffffffu, mx, k));
    float s = expf(o - mx);
    float tot = s;
    #pragma unroll
    for (int k = 8; k; k >>= 1) tot += __shfl_xor_sync(0xffffffffu, tot, k);
    out[(size_t)node * 16 + c] = o - mx - logf(tot);
}

// ---------------- launch ----------------
extern "C" void kernel_launch(void* const* d_in, const int* in_sizes, int n_in,
                              void* d_out, int out_size) {
    const float* x   = (const float*)d_in[0];
    const float* ea  = (const float*)d_in[1];
    const int*   src = (const int*)  d_in[2];
    const int*   dst = (const int*)  d_in[3];
    const float* W1  = (const float*)d_in[4];
    const float* R1  = (const float*)d_in[5];
    const float* b1  = (const float*)d_in[6];
    const float* Wa  = (const float*)d_in[7];
    const float* Ra  = (const float*)d_in[8];
    const float* ba  = (const float*)d_in[9];
    const float* Wb  = (const float*)d_in[10];
    const float* Rb  = (const float*)d_in[11];
    const float* bb  = (const float*)d_in[12];
    const float* W2  = (const float*)d_in[13];
    const float* R2  = (const float*)d_in[14];
    const float* b2  = (const float*)d_in[15];
    float* out = (float*)d_out;

    // CSR build
    k_zero_cnt<<<196, 256>>>();
    k_hist<<<3125, 256>>>(dst);
    k_scan1<<<49, 1024>>>();
    k_scan2<<<1, 64>>>();
    k_scan3<<<49, 1024>>>();
    k_scatter<<<3125, 256>>>(src, dst, ea);
    k_prep<<<150, 256>>>(W1, R1, Wa, Ra, Wb, Rb, W2, R2);

    dim3 g1(391, 3), gh(391, 1);

    // conv1
    gemm16<256, 192, 64, M_CONV1, 0, 0, 0><<<g1, 256>>>(x, nullptr);
    agg_post1<<<6250, 256>>>(b1);

    // RK4 stage 1
    agg_pre<0><<<6250, 256>>>();
    gemm16<192, 64, 64, M_PLAIN, 1, 1, 0><<<gh, 256>>>(nullptr, ba);
    agg_pre<1><<<6250, 256>>>();
    gemm16<192, 64, 64, M_K1, 1, 2, 1><<<gh, 256>>>(nullptr, bb);

    // stage 2
    agg_pre<2><<<6250, 256>>>();
    gemm16<192, 64, 64, M_PLAIN, 1, 1, 2><<<gh, 256>>>(nullptr, ba);
    agg_pre<1><<<6250, 256>>>();
    gemm16<192, 64, 64, M_K2, 1, 2, 1><<<gh, 256>>>(nullptr, bb);

    // stage 3
    agg_pre<2><<<6250, 256>>>();
    gemm16<192, 64, 64, M_PLAIN, 1, 1, 2><<<gh, 256>>>(nullptr, ba);
    agg_pre<1><<<6250, 256>>>();
    gemm16<192, 64, 64, M_K3, 1, 2, 1><<<gh, 256>>>(nullptr, bb);

    // stage 4
    agg_pre<2><<<6250, 256>>>();
    gemm16<192, 64, 64, M_PLAIN, 1, 1, 2><<<gh, 256>>>(nullptr, ba);
    agg_pre<1><<<6250, 256>>>();
    gemm16<192, 64, 64, M_K4, 1, 2, 1><<<gh, 256>>>(nullptr, bb);

    // conv2 + finish
    gemm16<64, 48, 48, M_CONV2, 2, 3, 0><<<gh, 256>>>(nullptr, nullptr);
    conv2_fin<<<3125, 256>>>(b2, out);
}

// round 3
// speedup vs baseline: 2.1671x; 1.6746x over previous
#include <cuda_runtime.h>
#include <cuda_bf16.h>
#include <cstdint>
#include <cstddef>

#define NN 50000
#define NE 800000

// ---------------- static device scratch ----------------
__device__ int   g_cnt[NN];
__device__ int   g_rowptr[NN + 1];
__device__ int   g_bsum[64];
__device__ int2  g_edge[NE];            // (src, float bits of p)
__device__ float g_invdeg[NN];

// bf16x2-packed tables (u32 each = 2 features)
__device__ __align__(16) unsigned g_uv1 [(size_t)NN * 64];  // conv1 u|v (128 feats)
__device__ __align__(16) unsigned g_h16 [(size_t)NN * 32];
__device__ __align__(16) unsigned g_a16 [(size_t)NN * 32];
__device__ __align__(16) unsigned g_y16 [(size_t)NN * 32];
__device__ __align__(16) unsigned g_hn16[(size_t)NN * 32];
__device__ __align__(16) unsigned g_acat[(size_t)NN * 64];  // A0|A1 (128 feats)
__device__ __align__(16) unsigned g_uv2 [(size_t)NN * 16];  // conv2 u|v (32 feats)

// fp32 state
__device__ float g_r1  [(size_t)NN * 64];
__device__ float g_hf  [(size_t)NN * 64];
__device__ float g_accf[(size_t)NN * 64];
__device__ float g_r2  [(size_t)NN * 16];

// packed weights
__device__ unsigned g_wc1[128 * 192];
__device__ unsigned g_wcA[96 * 64];
__device__ unsigned g_wcB[96 * 64];
__device__ unsigned g_wc2[32 * 48];

// ---------------- helpers ----------------
__device__ __forceinline__ void gds() {
#if __CUDA_ARCH__ >= 900
    cudaGridDependencySynchronize();
#endif
}
__device__ __forceinline__ unsigned pk(float a, float b) {
    __nv_bfloat162 h = __floats2bfloat162_rn(a, b);
    return *reinterpret_cast<unsigned*>(&h);
}
__device__ __forceinline__ float2 up(unsigned u) {
    __nv_bfloat162 h = *reinterpret_cast<__nv_bfloat162*>(&u);
    return make_float2(__bfloat162float(h.x), __bfloat162float(h.y));
}
__device__ __forceinline__ float bfh(unsigned u, int hi) {
    unsigned short s = hi ? (unsigned short)(u >> 16) : (unsigned short)(u & 0xffff);
    __nv_bfloat16 b = *reinterpret_cast<__nv_bfloat16*>(&s);
    return __bfloat162float(b);
}

// ---------------- init: zero cnt + pack weights ----------------
__global__ void k_init(const float* __restrict__ W1, const float* __restrict__ R1,
                       const float* __restrict__ Wa, const float* __restrict__ Ra,
                       const float* __restrict__ Wb, const float* __restrict__ Rb,
                       const float* __restrict__ W2, const float* __restrict__ R2) {
    gds();
    if (blockIdx.x < 196) {
        int i = blockIdx.x * 256 + threadIdx.x;
        if (i < NN) g_cnt[i] = 0;
        return;
    }
    int i = (blockIdx.x - 196) * 256 + threadIdx.x;
    if (i < 24576) {                        // g_wc1 [128][192], K=256
        int k2 = i / 192, c = i % 192;
        int ke = 2 * k2, ko = ke + 1;
        float e, o;
        if (c < 64)       { e = W1[ke * 64 + c];              o = W1[ko * 64 + c]; }
        else if (c < 128) { e = W1[(256 + ke) * 64 + c - 64];  o = W1[(256 + ko) * 64 + c - 64]; }
        else              { e = R1[ke * 64 + c - 128];         o = R1[ko * 64 + c - 128]; }
        g_wc1[i] = pk(e, o);
    } else if (i < 30720) {                 // g_wcA [96][64], K=192
        int j = i - 24576, k2 = j / 64, c = j % 64;
        int ke = 2 * k2, ko = ke + 1;
        float e = (ke < 128) ? Wa[ke * 64 + c] : Ra[(ke - 128) * 64 + c];
        float o = (ko < 128) ? Wa[ko * 64 + c] : Ra[(ko - 128) * 64 + c];
        g_wcA[j] = pk(e, o);
    } else if (i < 36864) {                 // g_wcB
        int j = i - 30720, k2 = j / 64, c = j % 64;
        int ke = 2 * k2, ko = ke + 1;
        float e = (ke < 128) ? Wb[ke * 64 + c] : Rb[(ke - 128) * 64 + c];
        float o = (ko < 128) ? Wb[ko * 64 + c] : Rb[(ko - 128) * 64 + c];
        g_wcB[j] = pk(e, o);
    } else if (i < 38400) {                 // g_wc2 [32][48], K=64
        int j = i - 36864, k2 = j / 48, c = j % 48;
        int ke = 2 * k2, ko = ke + 1;
        float e, o;
        if (c < 16)      { e = W2[ke * 16 + c];              o = W2[ko * 16 + c]; }
        else if (c < 32) { e = W2[(64 + ke) * 16 + c - 16];  o = W2[(64 + ko) * 16 + c - 16]; }
        else             { e = R2[ke * 16 + c - 32];         o = R2[ko * 16 + c - 32]; }
        g_wc2[j] = pk(e, o);
    }
}

// ---------------- CSR build ----------------
__global__ void k_hist(const int* __restrict__ dst) {
    gds();
    int e = blockIdx.x * 256 + threadIdx.x;
    if (e < NE) atomicAdd(&g_cnt[dst[e]], 1);
}

__global__ void k_scan1() {
    gds();
    __shared__ int ws[32];
    int tid = threadIdx.x, lane = tid & 31, wid = tid >> 5;
    int i = blockIdx.x * 1024 + tid;
    int v = (i < NN) ? g_cnt[i] : 0;
    int x = v;
    #pragma unroll
    for (int o = 1; o < 32; o <<= 1) {
        int t = __shfl_up_sync(0xffffffffu, x, o);
        if (lane >= o) x += t;
    }
    if (lane == 31) ws[wid] = x;
    __syncthreads();
    if (wid == 0) {
        int t = ws[lane];
        #pragma unroll
        for (int o = 1; o < 32; o <<= 1) {
            int u = __shfl_up_sync(0xffffffffu, t, o);
            if (lane >= o) t += u;
        }
        ws[lane] = t;
    }
    __syncthreads();
    int excl = x - v + (wid ? ws[wid - 1] : 0);
    if (i < NN) {
        g_rowptr[i] = excl;
        g_invdeg[i] = 1.0f / (float)max(v, 1);
        g_cnt[i] = 0;
    }
    if (tid == 1023) g_bsum[blockIdx.x] = excl + v;
}

__global__ void k_scan2() {
    gds();
    __shared__ int w2[2];
    int tid = threadIdx.x, lane = tid & 31, wid = tid >> 5;
    int v = (tid < 49) ? g_bsum[tid] : 0;
    int x = v;
    #pragma unroll
    for (int o = 1; o < 32; o <<= 1) {
        int t = __shfl_up_sync(0xffffffffu, x, o);
        if (lane >= o) x += t;
    }
    if (lane == 31) w2[wid] = x;
    __syncthreads();
    int incl = x + (wid == 1 ? w2[0] : 0);
    if (tid < 49) g_bsum[tid] = incl - v;
}

__global__ void k_scan3() {
    gds();
    int i = blockIdx.x * 1024 + threadIdx.x;
    if (i < NN) g_rowptr[i] += g_bsum[blockIdx.x];
    if (i == 0) g_rowptr[NN] = NE;
}

__global__ void k_scatter(const int* __restrict__ src, const int* __restrict__ dst,
                          const float* __restrict__ ea) {
    gds();
    int e = blockIdx.x * 256 + threadIdx.x;
    if (e < NE) {
        int d = dst[e];
        int pos = g_rowptr[d] + atomicAdd(&g_cnt[d], 1);
        g_edge[pos] = make_int2(src[e], __float_as_int(ea[e]));
    }
}

// ---------------- bf16 GEMM (m16n8k16) with fused epilogues ----------------
__device__ __forceinline__ void mma16(float* c, unsigned a0, unsigned a1, unsigned a2,
                                      unsigned a3, unsigned b0, unsigned b1) {
    asm volatile(
        "mma.sync.aligned.m16n8k16.row.col.f32.bf16.bf16.f32 "
        "{%0,%1,%2,%3},{%4,%5,%6,%7},{%8,%9},{%0,%1,%2,%3};"
        : "+f"(c[0]), "+f"(c[1]), "+f"(c[2]), "+f"(c[3])
        : "r"(a0), "r"(a1), "r"(a2), "r"(a3), "r"(b0), "r"(b1));
}

constexpr int M_CONV1 = 0, M_PLAIN = 1, M_K1 = 2, M_K2 = 3, M_K3 = 4, M_K4 = 5, M_CONV2 = 6;

template <int MODE>
__device__ __forceinline__ void epi_row(int gm, int gc, float v0, float v1,
                                        const float* __restrict__ bias) {
    if (gm >= NN) return;
    if constexpr (MODE == M_CONV1) {
        if (gc < 128) g_uv1[(size_t)gm * 64 + (gc >> 1)] = pk(v0, v1);
        else { g_r1[(size_t)gm * 64 + gc - 128] = v0; g_r1[(size_t)gm * 64 + gc - 127] = v1; }
    } else if constexpr (MODE == M_PLAIN) {
        g_a16[(size_t)gm * 32 + (gc >> 1)] = pk(v0 + bias[gc], v1 + bias[gc + 1]);
    } else if constexpr (MODE == M_K1) {
        size_t ix = (size_t)gm * 64 + gc;
        float k0 = v0 + bias[gc], k1 = v1 + bias[gc + 1];
        float h0 = g_hf[ix], h1 = g_hf[ix + 1];
        g_y16[(size_t)gm * 32 + (gc >> 1)] = pk(h0 + 1.5f * k0, h1 + 1.5f * k1);
        g_accf[ix] = h0 + 0.5f * k0; g_accf[ix + 1] = h1 + 0.5f * k1;
    } else if constexpr (MODE == M_K2) {
        size_t ix = (size_t)gm * 64 + gc;
        float k0 = v0 + bias[gc], k1 = v1 + bias[gc + 1];
        float h0 = g_hf[ix], h1 = g_hf[ix + 1];
        g_y16[(size_t)gm * 32 + (gc >> 1)] = pk(h0 + 1.5f * k0, h1 + 1.5f * k1);
        g_accf[ix] += k0; g_accf[ix + 1] += k1;
    } else if constexpr (MODE == M_K3) {
        size_t ix = (size_t)gm * 64 + gc;
        float k0 = v0 + bias[gc], k1 = v1 + bias[gc + 1];
        float h0 = g_hf[ix], h1 = g_hf[ix + 1];
        g_y16[(size_t)gm * 32 + (gc >> 1)] = pk(h0 + 3.0f * k0, h1 + 3.0f * k1);
        g_accf[ix] += k0; g_accf[ix + 1] += k1;
    } else if constexpr (MODE == M_K4) {
        size_t ix = (size_t)gm * 64 + gc;
        float k0 = v0 + bias[gc], k1 = v1 + bias[gc + 1];
        g_hn16[(size_t)gm * 32 + (gc >> 1)] = pk(g_accf[ix] + 0.5f * k0,
                                                 g_accf[ix + 1] + 0.5f * k1);
    } else {  // M_CONV2
        if (gc < 32) g_uv2[(size_t)gm * 16 + (gc >> 1)] = pk(v0, v1);
        else { g_r2[(size_t)gm * 16 + gc - 32] = v0; g_r2[(size_t)gm * 16 + gc - 31] = v1; }
    }
}

// ASEL: 0=conv1 (fp32 xin, K=256), 1=hidden (acat128 | ytab64), 2=conv2 (g_hn16)
template <int K, int NOUT, int BN, int MODE, int ASEL, int WSEL, int TSEL>
__global__ __launch_bounds__(256)
void gemm16(const float* __restrict__ xin, const float* __restrict__ bias) {
    gds();
    constexpr int NF = BN / 16;
    __shared__ __align__(16) unsigned As[128][36];
    __shared__ unsigned Bs[32][72];

    const unsigned* Wp = (WSEL == 0) ? g_wc1 : (WSEL == 1) ? g_wcA
                       : (WSEL == 2) ? g_wcB : g_wc2;
    const unsigned* ytab = (TSEL == 0) ? g_h16 : (TSEL == 1) ? g_a16 : g_y16;

    const int tid = threadIdx.x;
    const int m0 = blockIdx.x * 128;
    const int n0 = blockIdx.y * BN;
    const int wid = tid >> 5, lane = tid & 31;
    const int wm = (wid & 3) * 32;
    const int wn = (wid >> 2) * (BN / 2);
    const int g = lane >> 2, t = lane & 3;

    float acc[2][NF][4];
    #pragma unroll
    for (int i = 0; i < 2; i++)
        #pragma unroll
        for (int j = 0; j < NF; j++)
            #pragma unroll
            for (int e = 0; e < 4; e++) acc[i][j][e] = 0.f;

    for (int kc = 0; kc < K; kc += 64) {
        __syncthreads();
        if constexpr (ASEL == 0) {
            #pragma unroll
            for (int i = 0; i < 8; i++) {
                int q = tid + i * 256;
                int row = q >> 4, f4 = q & 15;
                int gm = m0 + row;
                float4 v = make_float4(0.f, 0.f, 0.f, 0.f);
                if (gm < NN)
                    v = *reinterpret_cast<const float4*>(xin + (size_t)gm * 256 + kc + f4 * 4);
                As[row][f4 * 2]     = pk(v.x, v.y);
                As[row][f4 * 2 + 1] = pk(v.z, v.w);
            }
        } else {
            #pragma unroll
            for (int i = 0; i < 4; i++) {
                int q = tid + i * 256;
                int row = q >> 3, q4 = q & 7;
                int gm = m0 + row;
                uint4 v = make_uint4(0, 0, 0, 0);
                if (gm < NN) {
                    const unsigned* p;
                    if constexpr (ASEL == 1)
                        p = (kc < 128) ? (g_acat + (size_t)gm * 64 + kc / 2 + q4 * 4)
                                       : (ytab + (size_t)gm * 32 + q4 * 4);
                    else
                        p = g_hn16 + (size_t)gm * 32 + q4 * 4;
                    v = *reinterpret_cast<const uint4*>(p);
                }
                *reinterpret_cast<uint4*>(&As[row][q4 * 4]) = v;
            }
        }
        constexpr int BITER = (32 * BN) / 256;
        #pragma unroll
        for (int i = 0; i < BITER; i++) {
            int q = tid + i * 256;
            int r = q / BN, n = q % BN;
            Bs[r][n] = Wp[(size_t)(kc / 2 + r) * NOUT + n0 + n];
        }
        __syncthreads();
        #pragma unroll
        for (int ks = 0; ks < 4; ks++) {
            const int kb = ks * 8;
            unsigned a[2][4];
            #pragma unroll
            for (int mf = 0; mf < 2; mf++) {
                a[mf][0] = As[wm + mf * 16 + g    ][kb + t];
                a[mf][1] = As[wm + mf * 16 + g + 8][kb + t];
                a[mf][2] = As[wm + mf * 16 + g    ][kb + 4 + t];
                a[mf][3] = As[wm + mf * 16 + g + 8][kb + 4 + t];
            }
            unsigned b[NF][2];
            #pragma unroll
            for (int nf = 0; nf < NF; nf++) {
                b[nf][0] = Bs[kb + t    ][wn + nf * 8 + g];
                b[nf][1] = Bs[kb + 4 + t][wn + nf * 8 + g];
            }
            #pragma unroll
            for (int mf = 0; mf < 2; mf++)
                #pragma unroll
                for (int nf = 0; nf < NF; nf++)
                    mma16(acc[mf][nf], a[mf][0], a[mf][1], a[mf][2], a[mf][3],
                          b[nf][0], b[nf][1]);
        }
    }

    #pragma unroll
    for (int mf = 0; mf < 2; mf++)
        #pragma unroll
        for (int nf = 0; nf < NF; nf++) {
            int gm0 = m0 + wm + mf * 16 + g;
            int gc  = n0 + wn + nf * 8 + t * 2;
            epi_row<MODE>(gm0,     gc, acc[mf][nf][0], acc[mf][nf][1], bias);
            epi_row<MODE>(gm0 + 8, gc, acc[mf][nf][2], acc[mf][nf][3], bias);
        }
}

// ---------------- aggregation (warp per node, bf16 gather) ----------------
__global__ __launch_bounds__(256)
void agg_post1(const float* __restrict__ b1) {
    gds();
    int node = (blockIdx.x << 3) + (threadIdx.x >> 5);
    int lane = threadIdx.x & 31;
    int beg = g_rowptr[node], end = g_rowptr[node + 1];
    float mx = 0.f, my = 0.f;
    int e = beg;
    for (; e + 2 <= end; e += 2) {
        int2 E0 = g_edge[e], E1 = g_edge[e + 1];
        float p0 = __int_as_float(E0.y), p1 = __int_as_float(E1.y);
        float2 u0 = up(g_uv1[(size_t)E0.x * 64 + lane]);
        float2 v0 = up(g_uv1[(size_t)E0.x * 64 + 32 + lane]);
        float2 u1 = up(g_uv1[(size_t)E1.x * 64 + lane]);
        float2 v1 = up(g_uv1[(size_t)E1.x * 64 + 32 + lane]);
        mx += (1.f - p0) * u0.x + p0 * v0.x + (1.f - p1) * u1.x + p1 * v1.x;
        my += (1.f - p0) * u0.y + p0 * v0.y + (1.f - p1) * u1.y + p1 * v1.y;
    }
    if (e < end) {
        int2 E0 = g_edge[e];
        float p0 = __int_as_float(E0.y);
        float2 u0 = up(g_uv1[(size_t)E0.x * 64 + lane]);
        float2 v0 = up(g_uv1[(size_t)E0.x * 64 + 32 + lane]);
        mx += (1.f - p0) * u0.x + p0 * v0.x;
        my += (1.f - p0) * u0.y + p0 * v0.y;
    }
    float id = g_invdeg[node];
    size_t ix = (size_t)node * 64 + lane * 2;
    float h0 = tanhf(mx * id + g_r1[ix]     + b1[lane * 2]);
    float h1 = tanhf(my * id + g_r1[ix + 1] + b1[lane * 2 + 1]);
    g_hf[ix] = h0; g_hf[ix + 1] = h1;
    g_h16[(size_t)node * 32 + lane] = pk(h0, h1);
}

template <int YSEL>  // 0=g_h16, 1=g_a16, 2=g_y16
__global__ __launch_bounds__(256)
void agg_pre() {
    gds();
    const unsigned* __restrict__ y = (YSEL == 0) ? g_h16 : (YSEL == 1) ? g_a16 : g_y16;
    int node = (blockIdx.x << 3) + (threadIdx.x >> 5);
    int lane = threadIdx.x & 31;
    int beg = g_rowptr[node], end = g_rowptr[node + 1];
    float a0x = 0.f, a0y = 0.f, a1x = 0.f, a1y = 0.f;
    int e = beg;
    for (; e + 4 <= end; e += 4) {
        int2 E0 = g_edge[e],     E1 = g_edge[e + 1];
        int2 E2 = g_edge[e + 2], E3 = g_edge[e + 3];
        float p0 = __int_as_float(E0.y), p1 = __int_as_float(E1.y);
        float p2 = __int_as_float(E2.y), p3 = __int_as_float(E3.y);
        float2 x0 = up(y[(size_t)E0.x * 32 + lane]);
        float2 x1 = up(y[(size_t)E1.x * 32 + lane]);
        float2 x2 = up(y[(size_t)E2.x * 32 + lane]);
        float2 x3 = up(y[(size_t)E3.x * 32 + lane]);
        a0x += (1.f - p0) * x0.x + (1.f - p1) * x1.x + (1.f - p2) * x2.x + (1.f - p3) * x3.x;
        a0y += (1.f - p0) * x0.y + (1.f - p1) * x1.y + (1.f - p2) * x2.y + (1.f - p3) * x3.y;
        a1x += p0 * x0.x + p1 * x1.x + p2 * x2.x + p3 * x3.x;
        a1y += p0 * x0.y + p1 * x1.y + p2 * x2.y + p3 * x3.y;
    }
    for (; e < end; e++) {
        int2 E0 = g_edge[e];
        float p0 = __int_as_float(E0.y);
        float2 x0 = up(y[(size_t)E0.x * 32 + lane]);
        a0x += (1.f - p0) * x0.x;
        a0y += (1.f - p0) * x0.y;
        a1x += p0 * x0.x;
        a1y += p0 * x0.y;
    }
    float id = g_invdeg[node];
    g_acat[(size_t)node * 64 + lane]      = pk(a0x * id, a0y * id);
    g_acat[(size_t)node * 64 + 32 + lane] = pk(a1x * id, a1y * id);
}

// conv2: gather + tanh + log_softmax(16); 16 threads per node
__global__ __launch_bounds__(256)
void conv2_fin(const float* __restrict__ b2, float* __restrict__ out) {
    gds();
    int node = blockIdx.x * 16 + (threadIdx.x >> 4);
    int c = threadIdx.x & 15;
    int beg = g_rowptr[node], end = g_rowptr[node + 1];
    float m = 0.f;
    int e = beg;
    for (; e + 2 <= end; e += 2) {
        int2 E0 = g_edge[e], E1 = g_edge[e + 1];
        float p0 = __int_as_float(E0.y), p1 = __int_as_float(E1.y);
        float u0 = bfh(g_uv2[(size_t)E0.x * 16 + (c >> 1)], c & 1);
        float v0 = bfh(g_uv2[(size_t)E0.x * 16 + 8 + (c >> 1)], c & 1);
        float u1 = bfh(g_uv2[(size_t)E1.x * 16 + (c >> 1)], c & 1);
        float v1 = bfh(g_uv2[(size_t)E1.x * 16 + 8 + (c >> 1)], c & 1);
        m += (1.f - p0) * u0 + p0 * v0 + (1.f - p1) * u1 + p1 * v1;
    }
    if (e < end) {
        int2 E0 = g_edge[e];
        float p0 = __int_as_float(E0.y);
        float u = bfh(g_uv2[(size_t)E0.x * 16 + (c >> 1)], c & 1);
        float v = bfh(g_uv2[(size_t)E0.x * 16 + 8 + (c >> 1)], c & 1);
        m += (1.f - p0) * u + p0 * v;
    }
    float o = tanhf(m * g_invdeg[node] + g_r2[(size_t)node * 16 + c] + b2[c]);
    float mx = o;
    #pragma unroll
    for (int k = 8; k; k >>= 1) mx = fmaxf(mx, __shfl_xor_sync(0xffffffffu, mx, k));
    float s = expf(o - mx);
    float tot = s;
    #pragma unroll
    for (int k = 8; k; k >>= 1) tot += __shfl_xor_sync(0xffffffffu, tot, k);
    out[(size_t)node * 16 + c] = o - mx - logf(tot);
}

// ---------------- launch helpers (PDL on every kernel) ----------------
template <typename F, typename... Args>
static inline void pdl(F f, dim3 grid, dim3 block, Args... args) {
    cudaLaunchConfig_t cfg = {};
    cfg.gridDim = grid;
    cfg.blockDim = block;
    cfg.dynamicSmemBytes = 0;
    cfg.stream = 0;
    cudaLaunchAttribute a[1];
    a[0].id = cudaLaunchAttributeProgrammaticStreamSerialization;
    a[0].val.programmaticStreamSerializationAllowed = 1;
    cfg.attrs = a;
    cfg.numAttrs = 1;
    cudaLaunchKernelEx(&cfg, f, args...);
}

extern "C" void kernel_launch(void* const* d_in, const int* in_sizes, int n_in,
                              void* d_out, int out_size) {
    const float* x   = (const float*)d_in[0];
    const float* ea  = (const float*)d_in[1];
    const int*   src = (const int*)  d_in[2];
    const int*   dst = (const int*)  d_in[3];
    const float* W1  = (const float*)d_in[4];
    const float* R1  = (const float*)d_in[5];
    const float* b1  = (const float*)d_in[6];
    const float* Wa  = (const float*)d_in[7];
    const float* Ra  = (const float*)d_in[8];
    const float* ba  = (const float*)d_in[9];
    const float* Wb  = (const float*)d_in[10];
    const float* Rb  = (const float*)d_in[11];
    const float* bb  = (const float*)d_in[12];
    const float* W2  = (const float*)d_in[13];
    const float* R2  = (const float*)d_in[14];
    const float* b2  = (const float*)d_in[15];
    float* out = (float*)d_out;

    // CSR build + weight prep
    pdl(k_init, dim3(346), dim3(256), W1, R1, Wa, Ra, Wb, Rb, W2, R2);
    pdl(k_hist, dim3(3125), dim3(256), dst);
    pdl(k_scan1, dim3(49), dim3(1024));
    pdl(k_scan2, dim3(1), dim3(64));
    pdl(k_scan3, dim3(49), dim3(1024));
    pdl(k_scatter, dim3(3125), dim3(256), src, dst, ea);

    dim3 g1(391, 3), gh(391, 1), ga(6250), gb(256);
    const float* np = nullptr;

    // conv1
    pdl(gemm16<256, 192, 64, M_CONV1, 0, 0, 0>, g1, gb, x, np);
    pdl(agg_post1, ga, gb, b1);

    // RK4 stage 1
    pdl(agg_pre<0>, ga, gb);
    pdl(gemm16<192, 64, 64, M_PLAIN, 1, 1, 0>, gh, gb, np, ba);
    pdl(agg_pre<1>, ga, gb);
    pdl(gemm16<192, 64, 64, M_K1, 1, 2, 1>, gh, gb, np, bb);

    // stage 2
    pdl(agg_pre<2>, ga, gb);
    pdl(gemm16<192, 64, 64, M_PLAIN, 1, 1, 2>, gh, gb, np, ba);
    pdl(agg_pre<1>, ga, gb);
    pdl(gemm16<192, 64, 64, M_K2, 1, 2, 1>, gh, gb, np, bb);

    // stage 3
    pdl(agg_pre<2>, ga, gb);
    pdl(gemm16<192, 64, 64, M_PLAIN, 1, 1, 2>, gh, gb, np, ba);
    pdl(agg_pre<1>, ga, gb);
    pdl(gemm16<192, 64, 64, M_K3, 1, 2, 1>, gh, gb, np, bb);

    // stage 4
    pdl(agg_pre<2>, ga, gb);
    pdl(gemm16<192, 64, 64, M_PLAIN, 1, 1, 2>, gh, gb, np, ba);
    pdl(agg_pre<1>, ga, gb);
    pdl(gemm16<192, 64, 64, M_K4, 1, 2, 1>, gh, gb, np, bb);

    // conv2 + finish
    pdl(gemm16<64, 48, 48, M_CONV2, 2, 3, 0>, gh, gb, np, np);
    pdl(conv2_fin, dim3(3125), gb, b2, out);
}